// round 11
// baseline (speedup 1.0000x reference)
#include <cuda_runtime.h>
#include <math.h>
#include <stdint.h>

#define LSEQ 2048
#define HD   512
#define BSZ  16

// ------------- device scratch (static; no runtime allocation) -------------
__device__ __align__(16) float d_P [11 * 4096];
__device__ __align__(16) float d_PT[11 * 4096];
__device__ __align__(16) float d_Bbar[64];
__device__ __align__(16) float d_W0 [64 * 64];
__device__ __align__(16) float d_Vr0[64 * 64];
__device__ __align__(16) float d_W[LSEQ * 64];    // w[s][n]
__device__ __align__(16) float d_V[LSEQ * 64];    // v[t][n] = C Abar^{L-1-t}

// =============== packed f32x2 helpers ===============
__device__ __forceinline__ uint64_t dup2(float x) {
    uint64_t r; uint32_t u = __float_as_uint(x);
    asm("mov.b64 %0, {%1, %1};" : "=l"(r) : "r"(u));
    return r;
}
__device__ __forceinline__ void fma2(uint64_t& d, uint64_t a, uint64_t b) {
    asm("fma.rn.f32x2 %0, %1, %2, %0;" : "+l"(d) : "l"(a), "l"(b));
}
__device__ __forceinline__ void add2(uint64_t& d, uint64_t a) {
    asm("add.rn.f32x2 %0, %0, %1;" : "+l"(d) : "l"(a));
}
__device__ __forceinline__ float2 un2(uint64_t v) {
    float2 r;
    asm("mov.b64 {%0, %1}, %2;" : "=f"(r.x), "=f"(r.y) : "l"(v));
    return r;
}
__device__ __forceinline__ void cpa16(uint32_t dst, const void* src) {
    asm volatile("cp.async.ca.shared.global [%0], [%1], 16;"
                 :: "r"(dst), "l"(__cvta_generic_to_global(src)));
}
__device__ __forceinline__ void cpa_commit() {
    asm volatile("cp.async.commit_group;");
}
__device__ __forceinline__ void cpa_wait0() {
    asm volatile("cp.async.wait_group 0;" ::: "memory");
}

// =============== setup: f32x2 64x64 matmul, 512 threads, transposed copies ===============
// C = A*B via AT (coalesced both operands). Writes C and CT.
// mode1: out = acc*scale + I (Horner step).
__device__ __forceinline__ void mm64T2(const float* __restrict__ AT, const float* __restrict__ B,
                                       float* __restrict__ C, float* __restrict__ CT,
                                       int tid, int mode, float scale) {
    int tx = tid & 15, ty = tid >> 4;    // tx 0..15, ty 0..31
    int j0 = tx << 2, i0 = ty << 1;      // 2 rows x 4 cols
    uint64_t acc[2][2];
    acc[0][0] = acc[0][1] = acc[1][0] = acc[1][1] = 0ull;
#pragma unroll 8
    for (int k = 0; k < 64; k++) {
        float2 av = *(const float2*)(AT + k * 64 + i0);
        ulonglong2 bv = *(const ulonglong2*)(B + k * 64 + j0);
        uint64_t a0 = dup2(av.x), a1 = dup2(av.y);
        fma2(acc[0][0], a0, bv.x); fma2(acc[0][1], a0, bv.y);
        fma2(acc[1][0], a1, bv.x); fma2(acc[1][1], a1, bv.y);
    }
    float o[2][4];
#pragma unroll
    for (int a = 0; a < 2; a++) {
        float2 p0 = un2(acc[a][0]);
        float2 p1 = un2(acc[a][1]);
        o[a][0] = p0.x; o[a][1] = p0.y; o[a][2] = p1.x; o[a][3] = p1.y;
        if (mode == 1) {
#pragma unroll
            for (int q = 0; q < 4; q++)
                o[a][q] = o[a][q] * scale + ((i0 + a) == (j0 + q) ? 1.f : 0.f);
        }
        float4 ov; ov.x = o[a][0]; ov.y = o[a][1]; ov.z = o[a][2]; ov.w = o[a][3];
        *(float4*)(C + (i0 + a) * 64 + j0) = ov;
    }
#pragma unroll
    for (int q = 0; q < 4; q++) {
        float2 tv; tv.x = o[0][q]; tv.y = o[1][q];
        *(float2*)(CT + (j0 + q) * 64 + i0) = tv;
    }
}

__global__ void __launch_bounds__(512, 1)
setup_kernel(const float* __restrict__ B_in, const float* __restrict__ logdt) {
    extern __shared__ float sm[];
    float* As  = sm;
    float* Xs  = sm + 4096;
    float* XsT = sm + 8192;
    float* R0  = sm + 12288;
    float* R0T = sm + 16384;
    float* R1  = sm + 20480;
    float* R1T = sm + 24576;
    __shared__ float colsum[64], rhs[64], bbsh[64], bsh[64];
    __shared__ int s_sh;
    int tid = threadIdx.x;

    double dt = exp((double)logdt[0]);
    for (int e = tid; e < 4096; e += 512) {
        int i = e >> 6, j = e & 63;
        float a = 0.f, x = 0.f;
        if (j <= i) {
            double pij = sqrt((1.0 + 2.0 * i) * (1.0 + 2.0 * j));
            double av = pij - (i == j ? (double)i : 0.0);
            a = (float)(-av);
            x = (float)(-av * dt);
        }
        As[e] = a; Xs[e] = x;
        XsT[(j << 6) + i] = x;
    }
    if (tid < 64) bsh[tid] = B_in[tid];
    __syncthreads();
    if (tid < 64) {
        float ssum = 0.f;
        for (int i = tid; i < 64; i++) ssum += fabsf(Xs[i * 64 + tid]);
        colsum[tid] = ssum;
    }
    __syncthreads();
    if (tid == 0) {
        float mx = 0.f;
        for (int j = 0; j < 64; j++) mx = fmaxf(mx, colsum[j]);
        int s = 0; float v = mx;
        while (v > 2.0f && s < 30) { v *= 0.5f; s++; }   // theta = 2 (deg-12 err 1.3e-6)
        s_sh = s;
    }
    __syncthreads();
    int s = s_sh;
    float scale = ldexpf(1.0f, -s);
    for (int e = tid; e < 4096; e += 512) { Xs[e] *= scale; XsT[e] *= scale; }
    __syncthreads();

    // Taylor deg-12 Horner: R = I + X/12; for k=11..1: R = I + (X*R)/k
    for (int e = tid; e < 4096; e += 512) {
        int i = e >> 6, j = e & 63;
        float d = (i == j) ? 1.f : 0.f;
        R0[e]  = Xs[e]  * (1.f / 12.f) + d;
        R0T[e] = XsT[e] * (1.f / 12.f) + d;
    }
    __syncthreads();
    float *cur = R0, *curT = R0T, *nxt = R1, *nxtT = R1T;
    for (int k = 11; k >= 1; k--) {
        mm64T2(XsT, cur, nxt, nxtT, tid, 1, 1.f / (float)k);
        __syncthreads();
        float* t;
        t = cur; cur = nxt; nxt = t;
        t = curT; curT = nxtT; nxtT = t;
    }
    for (int q = 0; q < s; q++) {
        mm64T2(curT, cur, nxt, nxtT, tid, 0, 0.f);
        __syncthreads();
        float* t;
        t = cur; cur = nxt; nxt = t;
        t = curT; curT = nxtT; nxtT = t;
    }
    if (tid < 64) {
        float acc = 0.f;
        for (int j = 0; j < 64; j++) {
            float p = cur[tid * 64 + j] - (tid == j ? 1.f : 0.f);
            acc = fmaf(p, bsh[j], acc);
        }
        rhs[tid] = acc;
    }
    __syncthreads();
    for (int e = tid; e < 4096; e += 512) { d_P[e] = cur[e]; d_PT[e] = curT[e]; }
    for (int k = 1; k < 11; k++) {
        mm64T2(curT, cur, nxt, nxtT, tid, 0, 0.f);
        __syncthreads();
        for (int e = tid; e < 4096; e += 512) {
            d_P [k * 4096 + e] = nxt[e];
            d_PT[k * 4096 + e] = nxtT[e];
        }
        float* t;
        t = cur; cur = nxt; nxt = t;
        t = curT; curT = nxtT; nxtT = t;
        __syncthreads();
    }
    float accv = (tid < 64) ? rhs[tid] : 0.f;
    for (int j = 0; j < 64; j++) {
        if (tid == j) bbsh[j] = accv / As[j * 64 + j];
        __syncthreads();
        if (tid < 64 && tid > j) accv = fmaf(-As[tid * 64 + j], bbsh[j], accv);
        __syncthreads();
    }
    if (tid < 64) d_Bbar[tid] = bbsh[tid];
}

// =============== stage A: Krylov doubling for first 64 w / vrev ===============
__global__ void __launch_bounds__(256, 1)
stageA_kernel(const float* __restrict__ C_in) {
    __shared__ float M[4096];
    __shared__ float Pb[4096];
    int tid = threadIdx.x;
    int isW = (blockIdx.x == 0);
    if (tid < 64) M[tid] = isW ? d_Bbar[tid] : C_in[tid];
    for (int k = 0; k < 6; k++) {
        const float* src = (isW ? d_PT : d_P) + k * 4096;
        __syncthreads();
        for (int f = tid; f < 1024; f += 256)
            ((float4*)Pb)[f] = __ldg((const float4*)src + f);
        __syncthreads();
        int half = 1 << k;
        for (int idx = tid; idx < half * 16; idx += 256) {
            int row = idx >> 4, n0 = (idx & 15) << 2;
            float4 acc = make_float4(0.f, 0.f, 0.f, 0.f);
            for (int m = 0; m < 64; m++) {
                float w = M[row * 64 + m];
                float4 p = *(const float4*)(Pb + m * 64 + n0);
                acc.x = fmaf(w, p.x, acc.x);
                acc.y = fmaf(w, p.y, acc.y);
                acc.z = fmaf(w, p.z, acc.z);
                acc.w = fmaf(w, p.w, acc.w);
            }
            *(float4*)(M + (half + row) * 64 + n0) = acc;
        }
    }
    __syncthreads();
    float* dst = isW ? d_W0 : d_Vr0;
    for (int f = tid; f < 1024; f += 256) ((float4*)dst)[f] = ((const float4*)M)[f];
}

// =============== chunk kernel ===============
__device__ __forceinline__ void mmg(const float* __restrict__ A, const float* __restrict__ B,
                                    float* __restrict__ out, int row0, int rowstep, int tid) {
    int tx = tid & 15, ty = tid >> 4;
    int j0 = tx << 2, i0 = ty << 2;
    float acc[4][4];
#pragma unroll
    for (int a = 0; a < 4; a++)
#pragma unroll
        for (int q = 0; q < 4; q++) acc[a][q] = 0.f;
#pragma unroll 8
    for (int k = 0; k < 64; k++) {
        float a0 = A[(i0 + 0) * 64 + k];
        float a1 = A[(i0 + 1) * 64 + k];
        float a2 = A[(i0 + 2) * 64 + k];
        float a3 = A[(i0 + 3) * 64 + k];
        float4 bv = *(const float4*)(B + k * 64 + j0);
        acc[0][0] = fmaf(a0, bv.x, acc[0][0]); acc[0][1] = fmaf(a0, bv.y, acc[0][1]);
        acc[0][2] = fmaf(a0, bv.z, acc[0][2]); acc[0][3] = fmaf(a0, bv.w, acc[0][3]);
        acc[1][0] = fmaf(a1, bv.x, acc[1][0]); acc[1][1] = fmaf(a1, bv.y, acc[1][1]);
        acc[1][2] = fmaf(a1, bv.z, acc[1][2]); acc[1][3] = fmaf(a1, bv.w, acc[1][3]);
        acc[2][0] = fmaf(a2, bv.x, acc[2][0]); acc[2][1] = fmaf(a2, bv.y, acc[2][1]);
        acc[2][2] = fmaf(a2, bv.z, acc[2][2]); acc[2][3] = fmaf(a2, bv.w, acc[2][3]);
        acc[3][0] = fmaf(a3, bv.x, acc[3][0]); acc[3][1] = fmaf(a3, bv.y, acc[3][1]);
        acc[3][2] = fmaf(a3, bv.z, acc[3][2]); acc[3][3] = fmaf(a3, bv.w, acc[3][3]);
    }
#pragma unroll
    for (int a = 0; a < 4; a++) {
        float4 o; o.x = acc[a][0]; o.y = acc[a][1]; o.z = acc[a][2]; o.w = acc[a][3];
        *(float4*)(out + (size_t)(row0 + rowstep * (i0 + a)) * 64 + j0) = o;
    }
}

__global__ void __launch_bounds__(256, 1)
chunk_kernel() {
    extern __shared__ float cs[];
    float* W0s  = cs;
    float* Vr0s = cs + 4096;
    float* Qa   = cs + 8192;
    float* Qb   = cs + 12288;
    float* QT   = cs + 16384;
    float* Pb   = cs + 20480;
    int tid = threadIdx.x;
    int c = blockIdx.x;

    for (int f = tid; f < 1024; f += 256) {
        ((float4*)W0s)[f]  = __ldg((const float4*)d_W0 + f);
        ((float4*)Vr0s)[f] = __ldg((const float4*)d_Vr0 + f);
    }
    __syncthreads();

    if (c == 0) {
        for (int f = tid; f < 1024; f += 256) ((float4*)d_W)[f] = ((const float4*)W0s)[f];
        for (int e = tid; e < 4096; e += 256) {
            int r = e >> 6, n = e & 63;
            d_V[(size_t)(2047 - r) * 64 + n] = Vr0s[e];
        }
        return;
    }

    int bits = c;
    int k0 = __ffs(bits) - 1; bits &= bits - 1;
    for (int f = tid; f < 1024; f += 256)
        ((float4*)Qa)[f] = __ldg((const float4*)(d_P + (6 + k0) * 4096) + f);
    float *qcur = Qa, *qnxt = Qb;
    while (bits) {
        int k = __ffs(bits) - 1; bits &= bits - 1;
        __syncthreads();
        for (int f = tid; f < 1024; f += 256)
            ((float4*)Pb)[f] = __ldg((const float4*)(d_P + (6 + k) * 4096) + f);
        __syncthreads();
        mmg(qcur, Pb, qnxt, 0, 1, tid);
        float* t = qcur; qcur = qnxt; qnxt = t;
    }
    __syncthreads();
    for (int e = tid; e < 4096; e += 256) {
        int i = e >> 6, j = e & 63;
        QT[j * 64 + i] = qcur[e];
    }
    __syncthreads();
    mmg(W0s, QT, d_W, 64 * c, 1, tid);
    mmg(Vr0s, qcur, d_V, 2047 - 64 * c, -1, tid);
}

// =============== main fused chunked-scan kernel ===============
// 512 threads, 4 roles x 128 threads, ONE barrier per chunk.
//   role 0: YA = V*Xcur  (K=64, 8i x 4h)        -> Yb[parity] (smem)
//   role 1: YB = Tz*U + D*U (K=64, 8i x 4h)     -> regs; post-barrier y = YA+YB -> gmem
//   role 2: Xnxt[n<32]  = Xcur + W^T U (K=64, 4n x 4h)  -> Xnxt (exclusive)
//   role 3: Xnxt[n>=32] = Xcur + W^T U (K=64, 4n x 4h)  -> Xnxt (exclusive)
// U/W double-buffered via cp.async; V via reg prefetch + transposed STS; Yb by parity.
__device__ __forceinline__ void g8x4(uint64_t acc[8][2], const float* __restrict__ A,
                                     const float* __restrict__ B, int k, int r0, int h0) {
    const float* ar = A + k * 64 + r0;
    float4 a03 = *(const float4*)ar;
    float4 a47 = *(const float4*)(ar + 4);
    ulonglong2 bv = *(const ulonglong2*)(B + k * 64 + h0);
    float av[8] = {a03.x, a03.y, a03.z, a03.w, a47.x, a47.y, a47.z, a47.w};
#pragma unroll
    for (int ai = 0; ai < 8; ai++) {
        uint64_t ad = dup2(av[ai]);
        fma2(acc[ai][0], ad, bv.x);
        fma2(acc[ai][1], ad, bv.y);
    }
}
__device__ __forceinline__ void g4x4(uint64_t acc[4][2], const float* __restrict__ A,
                                     const float* __restrict__ B, int k, int r0, int h0) {
    float4 a03 = *(const float4*)(A + k * 64 + r0);
    ulonglong2 bv = *(const ulonglong2*)(B + k * 64 + h0);
    float av[4] = {a03.x, a03.y, a03.z, a03.w};
#pragma unroll
    for (int ai = 0; ai < 4; ai++) {
        uint64_t ad = dup2(av[ai]);
        fma2(acc[ai][0], ad, bv.x);
        fma2(acc[ai][1], ad, bv.y);
    }
}

__global__ void __launch_bounds__(512, 1)
main_kernel(const float* __restrict__ u, const float* __restrict__ Dp, float* __restrict__ y) {
    extern __shared__ float sm[];
    float* Us0 = sm;            // [64][64]
    float* Us1 = sm + 4096;
    float* Ws0 = sm + 8192;
    float* Ws1 = sm + 12288;
    float* Vt0 = sm + 16384;    // V transposed [n][i]
    float* Vt1 = sm + 20480;
    float* Tz  = sm + 24576;    // TzT[j][i]
    float* Xb0 = sm + 28672;    // state ping
    float* Xb1 = sm + 32768;    // state pong
    float* Yb0 = sm + 36864;    // Y partial, parity 0
    float* Yb1 = sm + 40960;    // Y partial, parity 1

    int tid = threadIdx.x;
    int b = blockIdx.x >> 3;
    int habs = (blockIdx.x & 7) << 6;
    float Dv = Dp[0];
    uint64_t dv2 = dup2(Dv);

    uint32_t smem_u32 = (uint32_t)__cvta_generic_to_shared(sm);

    int role = tid >> 7;          // 0..3
    int t7 = tid & 127;
    // roles 0/1: 8i x 4h ; roles 2/3: 4n x 4h
    int r0y = (t7 >> 4) << 3;     // 0,8,...,56
    int r0x = ((t7 >> 4) << 2) + (role == 3 ? 32 : 0);  // role2: 0..28, role3: 32..60
    int h0 = (t7 & 15) << 2;      // 0,4,...,60

    // staging coords
    int vii = tid & 63, vng = tid >> 6;
    int n0v = vng << 3;

    const float* ub = u + (size_t)b * LSEQ * HD + habs;
    float*       yb = y + (size_t)b * LSEQ * HD + habs;

    // ---- zero X ping, stage chunk 0 (synchronous) ----
    for (int e = tid; e < 4096; e += 512) Xb0[e] = 0.f;
    for (int f = tid; f < 1024; f += 512) {
        int j = f >> 4, q = f & 15;
        ((float4*)Us0)[(j << 4) + q] = __ldg((const float4*)(ub + (size_t)j * HD) + q);
        ((float4*)Ws0)[f] = __ldg((const float4*)d_W + f);
    }
    {
        const float* Vrow = d_V + (size_t)vii * 64 + n0v;
#pragma unroll
        for (int q2 = 0; q2 < 2; q2++) {
            float4 v = *(const float4*)(Vrow + (q2 << 2));
            int nn = n0v + (q2 << 2);
            Vt0[(nn + 0) * 64 + vii] = v.x;
            Vt0[(nn + 1) * 64 + vii] = v.y;
            Vt0[(nn + 2) * 64 + vii] = v.z;
            Vt0[(nn + 3) * 64 + vii] = v.w;
        }
    }
    __syncthreads();

    // ---- one-time Toeplitz: Tz[j][i] = dot(v_i, w_j) masked i>=j ----
    {
        int jj = tid >> 3;
        int i0t = (tid & 7) << 3;
        float ta[8];
#pragma unroll
        for (int q = 0; q < 8; q++) ta[q] = 0.f;
#pragma unroll 4
        for (int n = 0; n < 64; n++) {
            float w = Ws0[jj * 64 + n];
            const float* vr = Vt0 + n * 64 + i0t;
            float4 v0 = *(const float4*)(vr);
            float4 v1 = *(const float4*)(vr + 4);
#pragma unroll
            for (int q = 0; q < 4; q++) {
                ta[q]     = fmaf(w, (&v0.x)[q], ta[q]);
                ta[4 + q] = fmaf(w, (&v1.x)[q], ta[4 + q]);
            }
        }
#pragma unroll
        for (int q = 0; q < 8; q++)
            Tz[jj * 64 + i0t + q] = (i0t + q >= jj) ? ta[q] : 0.f;
    }
    __syncthreads();

    float* Xc = Xb0;
    float* Xn = Xb1;

    for (int c = 0; c < 32; c++) {
        int p = c & 1;
        int tb = c << 6;
        const float* Uc = p ? Us1 : Us0;
        const float* Wc = p ? Ws1 : Ws0;
        const float* Vc = p ? Vt1 : Vt0;
        float* Ybp = p ? Yb1 : Yb0;
        uint32_t uAlt = smem_u32 + (p ? 0u : 4096u * 4u);
        uint32_t wAlt = smem_u32 + (p ? 8192u * 4u : 12288u * 4u);
        float*   vAlt = p ? Vt0 : Vt1;

        // ---- async prefetch next chunk: U and W via cp.async; V to regs ----
        float4 pv[2];
        if (c < 31) {
            int tbn = tb + 64;
#pragma unroll
            for (int it = 0; it < 2; it++) {
                int f = (it << 9) + tid;
                int j = f >> 4, q = f & 15;
                cpa16(uAlt + (uint32_t)((j << 6) + (q << 2)) * 4u,
                      ub + (size_t)(tbn + j) * HD + (q << 2));
                cpa16(wAlt + (uint32_t)((j << 6) + (q << 2)) * 4u,
                      d_W + (size_t)(tbn + j) * 64 + (q << 2));
            }
            cpa_commit();
            const float* Vrow = d_V + (size_t)(tbn + vii) * 64 + n0v;
#pragma unroll
            for (int q2 = 0; q2 < 2; q2++) pv[q2] = *(const float4*)(Vrow + (q2 << 2));
        }

        // ---- compute role partials ----
        uint64_t accY[8][2];   // roles 0,1
        uint64_t accX[4][2];   // roles 2,3
        if (role == 0) {
#pragma unroll
            for (int ai = 0; ai < 8; ai++) { accY[ai][0] = 0ull; accY[ai][1] = 0ull; }
#pragma unroll 4
            for (int n = 0; n < 64; n++) g8x4(accY, Vc, Xc, n, r0y, h0);
#pragma unroll
            for (int ai = 0; ai < 8; ai++) {
                ulonglong2 o; o.x = accY[ai][0]; o.y = accY[ai][1];
                *(ulonglong2*)(Ybp + (r0y + ai) * 64 + h0) = o;
            }
        } else if (role == 1) {
#pragma unroll
            for (int ai = 0; ai < 8; ai++) { accY[ai][0] = 0ull; accY[ai][1] = 0ull; }
#pragma unroll 4
            for (int j = 0; j < 64; j++) g8x4(accY, Tz, Uc, j, r0y, h0);
#pragma unroll
            for (int ai = 0; ai < 8; ai++) {
                ulonglong2 uv = *(const ulonglong2*)(Uc + (r0y + ai) * 64 + h0);
                fma2(accY[ai][0], dv2, uv.x);
                fma2(accY[ai][1], dv2, uv.y);
            }
        } else {
#pragma unroll
            for (int ai = 0; ai < 4; ai++) { accX[ai][0] = 0ull; accX[ai][1] = 0ull; }
#pragma unroll 4
            for (int j = 0; j < 64; j++) g4x4(accX, Wc, Uc, j, r0x, h0);
#pragma unroll
            for (int ai = 0; ai < 4; ai++) {
                ulonglong2 xv = *(const ulonglong2*)(Xc + (r0x + ai) * 64 + h0);
                add2(accX[ai][0], xv.x);
                add2(accX[ai][1], xv.y);
                ulonglong2 o; o.x = accX[ai][0]; o.y = accX[ai][1];
                *(ulonglong2*)(Xn + (r0x + ai) * 64 + h0) = o;
            }
        }

        // ---- V prefetch STS into alt buffer (all threads) ----
        if (c < 31) {
#pragma unroll
            for (int q2 = 0; q2 < 2; q2++) {
                int nn = n0v + (q2 << 2);
                vAlt[(nn + 0) * 64 + vii] = pv[q2].x;
                vAlt[(nn + 1) * 64 + vii] = pv[q2].y;
                vAlt[(nn + 2) * 64 + vii] = pv[q2].z;
                vAlt[(nn + 3) * 64 + vii] = pv[q2].w;
            }
            cpa_wait0();
        }
        __syncthreads();   // single barrier: Yb, Xn, new tiles all visible

        if (role == 1) {   // overlaps next chunk's compute in other warps
#pragma unroll
            for (int ai = 0; ai < 8; ai++) {
                ulonglong2 p1 = *(const ulonglong2*)(Ybp + (r0y + ai) * 64 + h0);
                add2(accY[ai][0], p1.x);
                add2(accY[ai][1], p1.y);
                ulonglong2 o; o.x = accY[ai][0]; o.y = accY[ai][1];
                *(ulonglong2*)(yb + (size_t)(tb + r0y + ai) * HD + h0) = o;
            }
        }

        float* t = Xc; Xc = Xn; Xn = t;
    }
}

extern "C" void kernel_launch(void* const* d_in, const int* in_sizes, int n_in,
                              void* d_out, int out_size) {
    const float* u      = (const float*)d_in[0];
    const float* B_ssm  = (const float*)d_in[1];
    const float* C_ssm  = (const float*)d_in[2];
    const float* D_skip = (const float*)d_in[3];
    const float* log_dt = (const float*)d_in[4];
    float* y = (float*)d_out;

    cudaFuncSetAttribute(setup_kernel, cudaFuncAttributeMaxDynamicSharedMemorySize, 114688);
    cudaFuncSetAttribute(chunk_kernel, cudaFuncAttributeMaxDynamicSharedMemorySize, 98304);
    cudaFuncSetAttribute(main_kernel,  cudaFuncAttributeMaxDynamicSharedMemorySize, 180224);

    setup_kernel<<<1, 512, 114688>>>(B_ssm, log_dt);
    stageA_kernel<<<2, 256>>>(C_ssm);
    chunk_kernel<<<32, 256, 98304>>>();
    main_kernel<<<BSZ * 8, 512, 180224>>>(u, D_skip, y);
}